// round 1
// baseline (speedup 1.0000x reference)
#include <cuda_runtime.h>

// Fixed problem shape (from setup_inputs)
#define BB 4
#define NC 1024
#define NF 8192
#define NG 8192

#define OFF_CX 0
#define OFF_CY (BB * NC)                      // 4096
#define OFF_FX (OFF_CY + BB * NG)             // 36864
#define OFF_FY (OFF_FX + BB * NG)             // 69632
#define MIN_TOTAL (OFF_FY + BB * NG)          // 102400

__device__ unsigned g_min[MIN_TOTAL];

// Monotone encoding: float -> uint such that float order == uint order.
__device__ __forceinline__ unsigned enc_f(float f) {
    unsigned u = __float_as_uint(f);
    return (u & 0x80000000u) ? ~u : (u | 0x80000000u);
}
__device__ __forceinline__ float dec_f(unsigned e) {
    unsigned u = (e & 0x80000000u) ? (e & 0x7FFFFFFFu) : ~e;
    return __uint_as_float(u);
}

__device__ __forceinline__ unsigned long long packf2(float lo, float hi) {
    float2 v = make_float2(lo, hi);
    return *reinterpret_cast<unsigned long long*>(&v);
}

__global__ void init_kernel() {
    int i = blockIdx.x * blockDim.x + threadIdx.x;
    if (i < MIN_TOTAL) g_min[i] = 0xFFFFFFFFu;
}

// For each x in X: min over y-chunk of v = 0.5*|y|^2 - x.y  (d = 2v + |x|^2)
// Each thread owns 2*NPAIRS x-points packed as f32x2; y broadcast from shared.
template<int NPAIRS, int YCHUNK>
__global__ void __launch_bounds__(256) chamfer_min_kernel(
    const float* __restrict__ X, const float* __restrict__ Y,
    int Nx, int Ny, int outOff)
{
    __shared__ float4 shA[YCHUNK];  // (y0,y0,y1,y1)
    __shared__ float4 shB[YCHUNK];  // (y2,y2,yh,yh)

    const int b = blockIdx.z;
    const int t = threadIdx.x;
    const int xbase = blockIdx.x * (256 * NPAIRS * 2);
    const int ybase = blockIdx.y * YCHUNK;

    // Cooperative load of y-chunk, duplicated for packed math.
    const float* Yb = Y + (size_t)b * Ny * 3;
    for (int j = t; j < YCHUNK; j += 256) {
        int yi = (ybase + j) * 3;
        float y0 = Yb[yi + 0], y1 = Yb[yi + 1], y2 = Yb[yi + 2];
        float yh = 0.5f * (y0 * y0 + y1 * y1 + y2 * y2);
        shA[j] = make_float4(y0, y0, y1, y1);
        shB[j] = make_float4(y2, y2, yh, yh);
    }

    // Load this thread's x-points (negated) into packed registers.
    const float* Xb = X + (size_t)b * Nx * 3;
    unsigned long long nx0[NPAIRS], nx1[NPAIRS], nx2[NPAIRS];
    float mlo[NPAIRS], mhi[NPAIRS];
    const float FINF = __int_as_float(0x7F800000);
#pragma unroll
    for (int p = 0; p < NPAIRS; p++) {
        int ia = (xbase + t + (2 * p) * 256) * 3;
        int ib = ia + 256 * 3;
        float a0 = -Xb[ia + 0], a1 = -Xb[ia + 1], a2 = -Xb[ia + 2];
        float c0 = -Xb[ib + 0], c1 = -Xb[ib + 1], c2 = -Xb[ib + 2];
        nx0[p] = packf2(a0, c0);
        nx1[p] = packf2(a1, c1);
        nx2[p] = packf2(a2, c2);
        mlo[p] = FINF;
        mhi[p] = FINF;
    }
    __syncthreads();

    const ulonglong2* pA = reinterpret_cast<const ulonglong2*>(shA);
    const ulonglong2* pB = reinterpret_cast<const ulonglong2*>(shB);

#pragma unroll 4
    for (int j = 0; j < YCHUNK; j++) {
        ulonglong2 Ay = pA[j];  // .x=(y0,y0) .y=(y1,y1)
        ulonglong2 By = pB[j];  // .x=(y2,y2) .y=(yh,yh)
#pragma unroll
        for (int p = 0; p < NPAIRS; p++) {
            unsigned long long v;
            asm("fma.rn.f32x2 %0, %1, %2, %3;"
                : "=l"(v) : "l"(nx2[p]), "l"(By.x), "l"(By.y));
            asm("fma.rn.f32x2 %0, %1, %2, %0;"
                : "+l"(v) : "l"(nx1[p]), "l"(Ay.y));
            asm("fma.rn.f32x2 %0, %1, %2, %0;"
                : "+l"(v) : "l"(nx0[p]), "l"(Ay.x));
            float2 vf = *reinterpret_cast<float2*>(&v);
            mlo[p] = fminf(mlo[p], vf.x);
            mhi[p] = fminf(mhi[p], vf.y);
        }
    }

    unsigned* outMin = g_min + outOff + b * Nx;
#pragma unroll
    for (int p = 0; p < NPAIRS; p++) {
        int ia = xbase + t + (2 * p) * 256;
        atomicMin(&outMin[ia], enc_f(mlo[p]));
        atomicMin(&outMin[ia + 256], enc_f(mhi[p]));
    }
}

__device__ __forceinline__ double decode_param(const int* p) {
    // Python int 1000 -> int32 bits (small magnitude). float 1000.0f bits are huge.
    int vi = *p;
    if (vi >= -(1 << 26) && vi <= (1 << 26)) return (double)vi;
    return (double)__int_as_float(vi);
}

__global__ void __launch_bounds__(512) finalize_kernel(
    const float* __restrict__ coarse, const float* __restrict__ fine,
    const float* __restrict__ gt, const int* pcv, const int* pfv,
    int has_params, float* __restrict__ out)
{
    __shared__ double red[512];
    const int t = threadIdx.x;

    float s0 = 0.f, s1 = 0.f, s2 = 0.f, s3 = 0.f, s4 = 0.f, s5 = 0.f, s6 = 0.f;
    for (int i = t; i < BB * NC; i += 512) s0 += dec_f(g_min[OFF_CX + i]);
    for (int i = t; i < BB * NG; i += 512) {
        s1 += dec_f(g_min[OFF_CY + i]);
        s2 += dec_f(g_min[OFF_FX + i]);
        s3 += dec_f(g_min[OFF_FY + i]);
    }
    for (int i = t; i < BB * NC * 3; i += 512) { float v = coarse[i]; s4 += v * v; }
    for (int i = t; i < BB * NF * 3; i += 512) {
        float v = fine[i]; s5 += v * v;
        float g = gt[i];   s6 += g * g;
    }

    float s[7] = {s0, s1, s2, s3, s4, s5, s6};
    double tot[7];
#pragma unroll
    for (int q = 0; q < 7; q++) {
        red[t] = (double)s[q];
        __syncthreads();
        for (int off = 256; off > 0; off >>= 1) {
            if (t < off) red[t] += red[t + off];
            __syncthreads();
        }
        tot[q] = red[0];
        __syncthreads();
    }

    if (t == 0) {
        double pc = has_params ? decode_param(pcv) : 1000.0;
        double pf = has_params ? decode_param(pfv) : 1000.0;
        // mean cham_x = (2*sum vmin + sum|x|^2) / (B*Nx)
        double cham_c = (2.0 * tot[0] + tot[4]) / (double)(BB * NC)
                      + (2.0 * tot[1] + tot[6]) / (double)(BB * NG);
        double cham_f = (2.0 * tot[2] + tot[5]) / (double)(BB * NF)
                      + (2.0 * tot[3] + tot[6]) / (double)(BB * NG);
        out[0] = (float)(cham_c * pc);
        out[1] = (float)(cham_f * pf);
    }
}

extern "C" void kernel_launch(void* const* d_in, const int* in_sizes, int n_in,
                              void* d_out, int out_size)
{
    const float* coarse = (const float*)d_in[0];
    const float* fine   = (const float*)d_in[1];
    const float* gt     = (const float*)d_in[2];
    const int* pc = (n_in > 3) ? (const int*)d_in[3] : nullptr;
    const int* pf = (n_in > 4) ? (const int*)d_in[4] : nullptr;
    float* out = (float*)d_out;

    init_kernel<<<(MIN_TOTAL + 255) / 256, 256>>>();

    // coarse vs gt: min over gt for each coarse point (NPAIRS=2 -> 1024-pt tile)
    chamfer_min_kernel<2, 256><<<dim3(1, NG / 256, BB), 256>>>(coarse, gt, NC, NG, OFF_CX);
    // min over coarse for each gt point
    chamfer_min_kernel<4, 256><<<dim3(NG / 2048, NC / 256, BB), 256>>>(gt, coarse, NG, NC, OFF_CY);
    // fine vs gt: both directions
    chamfer_min_kernel<4, 256><<<dim3(NF / 2048, NG / 256, BB), 256>>>(fine, gt, NF, NG, OFF_FX);
    chamfer_min_kernel<4, 256><<<dim3(NG / 2048, NF / 256, BB), 256>>>(gt, fine, NG, NF, OFF_FY);

    finalize_kernel<<<1, 512>>>(coarse, fine, gt, pc, pf, (n_in > 4) ? 1 : 0, out);
}

// round 2
// speedup vs baseline: 1.4607x; 1.4607x over previous
#include <cuda_runtime.h>

// Fixed problem shape (from setup_inputs)
#define BB 4
#define NC 1024
#define NF 8192
#define NG 8192
#define YCHUNK 256

#define OFF_CX 0
#define OFF_CY (BB * NC)                      // 4096
#define OFF_FX (OFF_CY + BB * NG)             // 36864
#define OFF_FY (OFF_FX + BB * NG)             // 69632
#define MIN_TOTAL (OFF_FY + BB * NG)          // 102400

__device__ unsigned g_min[MIN_TOTAL];
__device__ double g_acc[8];

// Monotone encoding: float -> uint such that float order == uint order.
__device__ __forceinline__ unsigned enc_f(float f) {
    unsigned u = __float_as_uint(f);
    return (u & 0x80000000u) ? ~u : (u | 0x80000000u);
}
__device__ __forceinline__ float dec_f(unsigned e) {
    unsigned u = (e & 0x80000000u) ? (e & 0x7FFFFFFFu) : ~e;
    return __uint_as_float(u);
}

__device__ __forceinline__ unsigned long long packf2(float lo, float hi) {
    float2 v = make_float2(lo, hi);
    return *reinterpret_cast<unsigned long long*>(&v);
}

__global__ void init_kernel() {
    int i = blockIdx.x * blockDim.x + threadIdx.x;
    if (i < MIN_TOTAL) g_min[i] = 0xFFFFFFFFu;
    if (i < 8) g_acc[i] = 0.0;
}

// For each x in X-tile: min over y-chunk of v = 0.5*|y|^2 - x.y  (d = 2v + |x|^2)
// Each thread owns 2*NP x-points packed as f32x2; y broadcast from shared.
template<int NP>
__device__ __forceinline__ void chamfer_body(
    const float* __restrict__ X, const float* __restrict__ Y,
    int Nx, int Ny, int outOff, int b, int xt, int yc,
    float4* shA, float4* shB)
{
    const int t = threadIdx.x;
    const int xbase = xt * (256 * NP * 2);
    const int ybase = yc * YCHUNK;

    // Cooperative load of y-chunk, duplicated for packed math.
    const float* Yb = Y + (size_t)b * Ny * 3;
    for (int j = t; j < YCHUNK; j += 256) {
        int yi = (ybase + j) * 3;
        float y0 = Yb[yi + 0], y1 = Yb[yi + 1], y2 = Yb[yi + 2];
        float yh = 0.5f * (y0 * y0 + y1 * y1 + y2 * y2);
        shA[j] = make_float4(y0, y0, y1, y1);
        shB[j] = make_float4(y2, y2, yh, yh);
    }

    // Load this thread's x-points (negated) into packed registers.
    const float* Xb = X + (size_t)b * Nx * 3;
    unsigned long long nx0[NP], nx1[NP], nx2[NP];
    float mlo[NP], mhi[NP];
    const float FINF = __int_as_float(0x7F800000);
#pragma unroll
    for (int p = 0; p < NP; p++) {
        int ia = (xbase + t + (2 * p) * 256) * 3;
        int ib = ia + 256 * 3;
        float a0 = -Xb[ia + 0], a1 = -Xb[ia + 1], a2 = -Xb[ia + 2];
        float c0 = -Xb[ib + 0], c1 = -Xb[ib + 1], c2 = -Xb[ib + 2];
        nx0[p] = packf2(a0, c0);
        nx1[p] = packf2(a1, c1);
        nx2[p] = packf2(a2, c2);
        mlo[p] = FINF;
        mhi[p] = FINF;
    }
    __syncthreads();

    const ulonglong2* pA = reinterpret_cast<const ulonglong2*>(shA);
    const ulonglong2* pB = reinterpret_cast<const ulonglong2*>(shB);

#pragma unroll 8
    for (int j = 0; j < YCHUNK; j++) {
        ulonglong2 Ay = pA[j];  // .x=(y0,y0) .y=(y1,y1)
        ulonglong2 By = pB[j];  // .x=(y2,y2) .y=(yh,yh)
#pragma unroll
        for (int p = 0; p < NP; p++) {
            unsigned long long v;
            asm("fma.rn.f32x2 %0, %1, %2, %3;"
                : "=l"(v) : "l"(nx2[p]), "l"(By.x), "l"(By.y));
            asm("fma.rn.f32x2 %0, %1, %2, %0;"
                : "+l"(v) : "l"(nx1[p]), "l"(Ay.y));
            asm("fma.rn.f32x2 %0, %1, %2, %0;"
                : "+l"(v) : "l"(nx0[p]), "l"(Ay.x));
            float2 vf = *reinterpret_cast<float2*>(&v);
            mlo[p] = fminf(mlo[p], vf.x);
            mhi[p] = fminf(mhi[p], vf.y);
        }
    }

    unsigned* outMin = g_min + outOff + b * Nx;
#pragma unroll
    for (int p = 0; p < NP; p++) {
        int ia = xbase + t + (2 * p) * 256;
        atomicMin(&outMin[ia], enc_f(mlo[p]));
        atomicMin(&outMin[ia + 256], enc_f(mhi[p]));
    }
}

// Flat block decode over all 4 chamfer directions:
//   dir0 FX (fine vs gt,   NP=4): 4 xtiles * 32 ychunks * 4 b = 512 blocks
//   dir1 FY (gt vs fine,   NP=4): 512 blocks
//   dir2 CX (coarse vs gt, NP=2): 1 xtile * 32 ychunks * 4 b  = 128 blocks
//   dir3 CY (gt vs coarse, NP=4): 4 xtiles * 4 ychunks * 4 b  = 64 blocks
#define TOTAL_BLOCKS 1216

__global__ void __launch_bounds__(256) fused_chamfer_kernel(
    const float* __restrict__ coarse, const float* __restrict__ fine,
    const float* __restrict__ gt)
{
    __shared__ float4 shA[YCHUNK];
    __shared__ float4 shB[YCHUNK];
    int id = blockIdx.x;
    if (id < 512) {
        int b = id >> 7, r = id & 127, xt = r >> 5, yc = r & 31;
        chamfer_body<4>(fine, gt, NF, NG, OFF_FX, b, xt, yc, shA, shB);
    } else if (id < 1024) {
        id -= 512;
        int b = id >> 7, r = id & 127, xt = r >> 5, yc = r & 31;
        chamfer_body<4>(gt, fine, NG, NF, OFF_FY, b, xt, yc, shA, shB);
    } else if (id < 1152) {
        id -= 1024;
        int b = id >> 5, yc = id & 31;
        chamfer_body<2>(coarse, gt, NC, NG, OFF_CX, b, 0, yc, shA, shB);
    } else {
        id -= 1152;
        int b = id >> 4, r = id & 15, xt = r >> 2, yc = r & 3;
        chamfer_body<4>(gt, coarse, NG, NC, OFF_CY, b, xt, yc, shA, shB);
    }
}

__global__ void __launch_bounds__(256) reduce_kernel(
    const float* __restrict__ coarse, const float* __restrict__ fine,
    const float* __restrict__ gt)
{
    const int tid = blockIdx.x * blockDim.x + threadIdx.x;
    const int stride = gridDim.x * blockDim.x;

    double s[7] = {0, 0, 0, 0, 0, 0, 0};
    for (int i = tid; i < BB * NC; i += stride) s[0] += (double)dec_f(g_min[OFF_CX + i]);
    for (int i = tid; i < BB * NG; i += stride) {
        s[1] += (double)dec_f(g_min[OFF_CY + i]);
        s[2] += (double)dec_f(g_min[OFF_FX + i]);
        s[3] += (double)dec_f(g_min[OFF_FY + i]);
    }
    for (int i = tid; i < BB * NC * 3; i += stride) {
        float v = coarse[i]; s[4] += (double)v * (double)v;
    }
    for (int i = tid; i < BB * NF * 3; i += stride) {
        float v = fine[i]; s[5] += (double)v * (double)v;
        float g = gt[i];   s[6] += (double)g * (double)g;
    }

#pragma unroll
    for (int q = 0; q < 7; q++) {
#pragma unroll
        for (int o = 16; o > 0; o >>= 1)
            s[q] += __shfl_down_sync(0xFFFFFFFFu, s[q], o);
    }
    if ((threadIdx.x & 31) == 0) {
#pragma unroll
        for (int q = 0; q < 7; q++) atomicAdd(&g_acc[q], s[q]);
    }
}

__device__ __forceinline__ double decode_param(const int* p) {
    // Python int 1000 -> int32 bits (small magnitude). float 1000.0f bits are huge.
    int vi = *p;
    if (vi >= -(1 << 26) && vi <= (1 << 26)) return (double)vi;
    return (double)__int_as_float(vi);
}

__global__ void final_kernel(const int* pcv, const int* pfv, int has_params,
                             float* __restrict__ out)
{
    double pc = has_params ? decode_param(pcv) : 1000.0;
    double pf = has_params ? decode_param(pfv) : 1000.0;
    // mean cham_x = (2*sum vmin + sum|x|^2) / (B*Nx)
    double cham_c = (2.0 * g_acc[0] + g_acc[4]) / (double)(BB * NC)
                  + (2.0 * g_acc[1] + g_acc[6]) / (double)(BB * NG);
    double cham_f = (2.0 * g_acc[2] + g_acc[5]) / (double)(BB * NF)
                  + (2.0 * g_acc[3] + g_acc[6]) / (double)(BB * NG);
    out[0] = (float)(cham_c * pc);
    out[1] = (float)(cham_f * pf);
}

extern "C" void kernel_launch(void* const* d_in, const int* in_sizes, int n_in,
                              void* d_out, int out_size)
{
    const float* coarse = (const float*)d_in[0];
    const float* fine   = (const float*)d_in[1];
    const float* gt     = (const float*)d_in[2];
    const int* pc = (n_in > 3) ? (const int*)d_in[3] : nullptr;
    const int* pf = (n_in > 4) ? (const int*)d_in[4] : nullptr;
    float* out = (float*)d_out;

    init_kernel<<<(MIN_TOTAL + 255) / 256, 256>>>();
    fused_chamfer_kernel<<<TOTAL_BLOCKS, 256>>>(coarse, fine, gt);
    reduce_kernel<<<64, 256>>>(coarse, fine, gt);
    final_kernel<<<1, 1>>>(pc, pf, (n_in > 4) ? 1 : 0, out);
}